// round 3
// baseline (speedup 1.0000x reference)
#include <cuda_runtime.h>

// Fast Hadamard Transform, DIM = 4096, fp32.
// 128 threads per row, 32 elements per thread.
//   Pass 1 (regs, FWHT-32): element bits {11,10,9,1,0}   (float4-coalesced loads)
//   one XOR-swizzled SMEM exchange (natural element order in smem)
//   Pass 2 (regs, FWHT-32): element bits {8..4}
//   2 shuffle-FWHT stages:  element bits {3,2}           (lane bits 2,3)
// Low register footprint (32 data regs) -> high occupancy -> DRAM overlap.

#define FWHT_DIM 4096
#define THREADS 128

// scale = 2^-(L(L+1)/4) with L=12 -> 2^-39
#define FWHT_SCALE 0x1p-39f

__device__ __forceinline__ void fwht32(float r[32]) {
#pragma unroll
    for (int h = 1; h < 32; h <<= 1) {
#pragma unroll
        for (int k = 0; k < 32; k++) {
            if (!(k & h)) {
                float a = r[k];
                float b = r[k ^ h];
                r[k]     = a + b;
                r[k ^ h] = a - b;
            }
        }
    }
}

// smem swizzle: phys = a ^ (bit9(a) << 4)  (XOR by 16 floats = 64B, keeps
// 16B alignment for float4 accesses)
__device__ __forceinline__ int swz(int a) { return a ^ (((a >> 9) & 1) << 4); }

__global__ void __launch_bounds__(THREADS)
fwht4096_kernel(const float* __restrict__ x, float* __restrict__ out) {
    __shared__ float s[FWHT_DIM];   // 16 KB, natural element order (swizzled)

    const int t    = threadIdx.x;        // 0..127, t = i[8:2] at load time
    const int lane = t & 31;

    const size_t row_off = (size_t)blockIdx.x * FWHT_DIM;
    const float* __restrict__ xr = x + row_off;
    float* __restrict__ yr = out + row_off;

    float r[32];

    // ---- Load + Pass 1: reg j = k*4+q -> bits j[4:2]=i[11:9], j[1:0]=i[1:0]
    // 8 independent LDG.128, fully coalesced (each warp inst covers 512B).
#pragma unroll
    for (int k = 0; k < 8; k++) {
        float4 v = *reinterpret_cast<const float4*>(xr + k * 512 + t * 4);
        r[k * 4 + 0] = v.x;
        r[k * 4 + 1] = v.y;
        r[k * 4 + 2] = v.z;
        r[k * 4 + 3] = v.w;
    }
    fwht32(r);   // transforms element bits {11,10,9,1,0}

    // ---- SMEM write (natural order, swizzled): a = k*512 + t*4 (+q) ----
    // STS.128; per-inst addresses are 128B-contiguous per warp ^ warp-constant
    // -> conflict-free.
#pragma unroll
    for (int k = 0; k < 8; k++) {
        int a = k * 512 + t * 4;
        *reinterpret_cast<float4*>(s + swz(a)) =
            make_float4(r[k * 4 + 0], r[k * 4 + 1], r[k * 4 + 2], r[k * 4 + 3]);
    }
    __syncthreads();

    // ---- SMEM read: regs j' = i[8:4]; thread fixes i[11:10]=t[6:5],
    // i9=lane[4], i[3:0]=lane[3:0].  a = base + j'*16.
    // banks(fixed j') = i[3:0] + ((i9 ^ j'0) << 4): bijection -> conflict-free.
    const int base = ((t >> 5) << 10)      // i[11:10] * 1024
                   + ((t & 16) << 5)       // i9 * 512
                   + (t & 15);             // i[3:0]
#pragma unroll
    for (int j = 0; j < 32; j++) {
        r[j] = s[swz(base + j * 16)];
    }

    // ---- Pass 2: transforms element bits {8..4} ----
    fwht32(r);

    // ---- Shuffle-FWHT over element bits {2,3} = lane bits {2,3} ----
#pragma unroll
    for (int m = 4; m <= 8; m <<= 1) {
        const bool hi = (lane & m) != 0;
#pragma unroll
        for (int j = 0; j < 32; j++) {
            float p = __shfl_xor_sync(0xffffffffu, r[j], m, 32);
            r[j] = hi ? (p - r[j]) : (r[j] + p);
        }
    }

    // ---- Scale + store ----
    // Per STG.32 inst: lanes cover i[3:0] (64B run) x i9 (stride 2KB):
    // two full-sector 64B runs -> no write amplification.
    float* __restrict__ yw = yr + base;
#pragma unroll
    for (int j = 0; j < 32; j++) {
        yw[j * 16] = r[j] * FWHT_SCALE;
    }
}

extern "C" void kernel_launch(void* const* d_in, const int* in_sizes, int n_in,
                              void* d_out, int out_size) {
    const float* x = (const float*)d_in[0];
    float* out = (float*)d_out;
    const int rows = in_sizes[0] / FWHT_DIM;   // 8192
    fwht4096_kernel<<<rows, THREADS>>>(x, out);
}